// round 7
// baseline (speedup 1.0000x reference)
#include <cuda_runtime.h>
#include <float.h>

// Problem constants
#define BB 64
#define AA 8732
#define CC 81
#define NANCH (BB * AA)          // 558848
#define BPI 69                   // closs blocks per image (69*128 >= 8732)
#define TROWS 128
#define NBLK1 (BB * BPI)         // 4416
#define TILE_F (TROWS * CC)      // 10368 floats
#define AA4 (AA / 4)             // 2183

// Scratch (no allocations allowed)
__device__ float    g_conf[NANCH];        // conf_neg (masked closs)
__device__ float4   g_part[NBLK1];        // per closs-block: {loc, pcl, cnt, -}
__device__ unsigned g_hist[BB][2048];     // per-image 11-bit MSB histogram
__device__ float    g_img[BB * 4];        // per image: loc, pcl, neg_topk, cnt
__device__ int      g_mask_is_bytes;
__device__ unsigned g_ticket;

// ---------------------------------------------------------------------------
// Zero/reset kernel: clears hist + flags (graph replays need re-zeroing).
// 64x256 threads, 8 ints each = 131072 = 64*2048 exactly.
// ---------------------------------------------------------------------------
__global__ void zero_kernel()
{
    const int i = blockIdx.x * blockDim.x + threadIdx.x;
    unsigned* h = &g_hist[0][0];
    #pragma unroll
    for (int k = 0; k < 8; k++) h[i + k * 16384] = 0u;
    if (i == 0) { g_mask_is_bytes = 0; g_ticket = 0u; }
}

// ---------------------------------------------------------------------------
// Mask dtype probe over first 16384 words (64KB region). If mask is bool
// bytes, ~1300 positive bytes land there -> certain; int32 mask is all 0/1.
// ---------------------------------------------------------------------------
__global__ void probe_kernel(const int* __restrict__ m)
{
    const int i = blockIdx.x * blockDim.x + threadIdx.x;   // 16384 threads
    if ((unsigned)m[i] > 1u) atomicOr(&g_mask_is_bytes, 1);
}

// ---------------------------------------------------------------------------
// Kernel 1 (fused): per-anchor CE -> conf_neg + per-image hist + per-block
// partial sums (loc/pcl/cnt). Per-image tiled grid: block = (img, 128 rows).
// Stage rows into shared (coalesced f4), thread-per-anchor logsumexp
// (no max-subtraction: scores ~N(0,1), fp32-safe). Deterministic: int
// atomics only; partial sums go to fixed slots, summed in fixed trees.
// ---------------------------------------------------------------------------
__global__ __launch_bounds__(128) void closs_kernel(const float4* __restrict__ scores4,
                                                    const int* __restrict__ labels,
                                                    const float4* __restrict__ boxes,
                                                    const float4* __restrict__ gtb,
                                                    const int* __restrict__ mask_i,
                                                    const unsigned char* __restrict__ mask_b)
{
    __shared__ __align__(16) float tile[TILE_F];   // 41472 B
    __shared__ float sred[12];

    const int img  = blockIdx.x / BPI;
    const int blk  = blockIdx.x - img * BPI;
    const int row0 = blk * TROWS;
    const int rows = min(TROWS, AA - row0);        // 128, tail block 28
    const int t    = threadIdx.x;
    const int anchor = img * AA + row0 + t;

    const float4* src = scores4 + ((size_t)img * AA + row0) * CC / 4;  // always f4-aligned
    const int nf4 = rows * CC / 4;                 // rows*81 divisible by 4
    float4* t4 = (float4*)tile;
    for (int i = t; i < nf4; i += 128) t4[i] = src[i];

    // independent loads (overlap with staging)
    int lab = 0; bool mk = false;
    if (t < rows) {
        lab = labels[anchor];
        mk  = g_mask_is_bytes ? (mask_b[anchor] != 0) : (mask_i[anchor] != 0);
    }
    __syncthreads();

    float cnt = 0.0f, pcl = 0.0f, loc = 0.0f;
    if (t < rows) {
        const float* p = tile + t * CC;   // stride 81 (odd) -> conflict-free
        float s0 = 0.0f, s1 = 0.0f, s2 = 0.0f, s3 = 0.0f;
        #pragma unroll
        for (int c = 0; c < 80; c += 4) {
            s0 += __expf(p[c]);
            s1 += __expf(p[c + 1]);
            s2 += __expf(p[c + 2]);
            s3 += __expf(p[c + 3]);
        }
        s0 += __expf(p[80]);
        const float cl = __logf((s0 + s1) + (s2 + s3)) - p[lab];

        const float conf = mk ? 0.0f : fmaxf(cl, 0.0f);   // cl>0 mathematically
        g_conf[anchor] = conf;
        atomicAdd(&g_hist[img][__float_as_uint(conf) >> 21], 1u);

        if (mk) {
            cnt = 1.0f; pcl = cl;
            float4 bx = boxes[anchor], gx = gtb[anchor];
            float d, ad;
            d = bx.x - gx.x; ad = fabsf(d); loc += (ad < 1.0f) ? 0.5f*d*d : ad - 0.5f;
            d = bx.y - gx.y; ad = fabsf(d); loc += (ad < 1.0f) ? 0.5f*d*d : ad - 0.5f;
            d = bx.z - gx.z; ad = fabsf(d); loc += (ad < 1.0f) ? 0.5f*d*d : ad - 0.5f;
            d = bx.w - gx.w; ad = fabsf(d); loc += (ad < 1.0f) ? 0.5f*d*d : ad - 0.5f;
        }
    }

    // block partial reduce (fixed tree; tail threads contribute 0)
    #pragma unroll
    for (int o = 16; o > 0; o >>= 1) {
        cnt += __shfl_xor_sync(0xFFFFFFFFu, cnt, o);
        pcl += __shfl_xor_sync(0xFFFFFFFFu, pcl, o);
        loc += __shfl_xor_sync(0xFFFFFFFFu, loc, o);
    }
    if ((t & 31) == 0) {
        const int w = t >> 5;
        sred[w * 3 + 0] = loc; sred[w * 3 + 1] = pcl; sred[w * 3 + 2] = cnt;
    }
    __syncthreads();
    if (t == 0) {
        g_part[blockIdx.x] = make_float4(sred[0] + sred[3] + sred[6] + sred[9],
                                         sred[1] + sred[4] + sred[7] + sred[10],
                                         sred[2] + sred[5] + sred[8] + sred[11],
                                         0.0f);
    }
}

// ---------------------------------------------------------------------------
// Block sum reduction (1024 threads): shuffle + 32-entry shared, deterministic.
// ---------------------------------------------------------------------------
__device__ __forceinline__ float block_reduce_sum(float v, float* sbuf)
{
    const int lane = threadIdx.x & 31, wid = threadIdx.x >> 5;
    #pragma unroll
    for (int o = 16; o > 0; o >>= 1) v += __shfl_xor_sync(0xFFFFFFFFu, v, o);
    if (lane == 0) sbuf[wid] = v;
    __syncthreads();
    if (wid == 0) {
        v = sbuf[lane];
        #pragma unroll
        for (int o = 16; o > 0; o >>= 1) v += __shfl_xor_sync(0xFFFFFFFFu, v, o);
        if (lane == 0) sbuf[0] = v;
    }
    __syncthreads();
    float r = sbuf[0];
    __syncthreads();
    return r;
}

// ---------------------------------------------------------------------------
// Descending-bin radix selection over NB bins (cs bins/thread, cs in {1,2});
// blockDim 1024. Deterministic (single boundary thread writes).
// ---------------------------------------------------------------------------
__device__ __forceinline__ void select_desc(const unsigned* __restrict__ hist,
                                            int NB, int cs, unsigned Kr,
                                            unsigned* wscan,
                                            unsigned* sh_sel, unsigned* sh_rr)
{
    const int tid = threadIdx.x, lane = tid & 31, wid = tid >> 5;
    unsigned cv0 = 0, cv1 = 0, v;
    const int hi = NB - 1 - cs * tid;
    cv0 = hist[hi];
    if (cs == 2) cv1 = hist[hi - 1];
    v = cv0 + cv1;

    unsigned incl = v;
    #pragma unroll
    for (int st = 1; st < 32; st <<= 1) {
        unsigned o = __shfl_up_sync(0xFFFFFFFFu, incl, st);
        if (lane >= st) incl += o;
    }
    if (lane == 31) wscan[wid] = incl;
    __syncthreads();
    if (wid == 0) {
        unsigned wv = wscan[lane];
        unsigned wi = wv;
        #pragma unroll
        for (int st = 1; st < 32; st <<= 1) {
            unsigned o = __shfl_up_sync(0xFFFFFFFFu, wi, st);
            if (lane >= st) wi += o;
        }
        wscan[lane] = wi - wv;
    }
    __syncthreads();
    const unsigned excl  = wscan[wid] + incl - v;
    const unsigned inclT = wscan[wid] + incl;
    if (excl < Kr && inclT >= Kr) {
        unsigned cum = excl;
        if (cum + cv0 >= Kr)      { *sh_sel = (unsigned)hi;       *sh_rr = Kr - cum; }
        else                      { cum += cv0;
                                    *sh_sel = (unsigned)(hi - 1); *sh_rr = Kr - cum; }
    }
    __syncthreads();
}

// ---------------------------------------------------------------------------
// Kernel 2: one block per image. Hist prebuilt by closs; conf_neg prebuilt.
// Select threshold bin, refine over candidates, strict-greater sum.
// Last block (ticket) folds the cross-image finalize.
// ---------------------------------------------------------------------------
#define SM_SV    0
#define SM_HIST  34928
#define SM_CAND  43120
#define SM_WSCAN 60584
#define SM_SBUF  60712
#define SM_SCAL  60840
#define TK_SMEM  (60840 + 64)

__global__ __launch_bounds__(1024) void topk_kernel(float* __restrict__ out)
{
    extern __shared__ __align__(16) unsigned char sm[];
    float*          svals = (float*)(sm + SM_SV);        // [8732]
    unsigned*       hist  = (unsigned*)(sm + SM_HIST);   // [2048]
    unsigned short* cand  = (unsigned short*)(sm + SM_CAND);  // [8732]
    unsigned*       wscan = (unsigned*)(sm + SM_WSCAN);  // [32]
    float*          sbuf  = (float*)(sm + SM_SBUF);      // [32]
    unsigned*       scal  = (unsigned*)(sm + SM_SCAL);   // [16]
    float*          fscal = (float*)(sm + SM_SCAL);      // aliased: [8..10] floats

    const int b = blockIdx.x, tid = threadIdx.x;

    // load conf_neg into smem (2183 f4)
    const float4* c4 = (const float4*)(g_conf + b * AA);
    float4* s4 = (float4*)svals;
    s4[tid]        = c4[tid];
    s4[tid + 1024] = c4[tid + 1024];
    if (tid < AA4 - 2048) s4[tid + 2048] = c4[tid + 2048];

    // load prebuilt histogram
    hist[tid]        = g_hist[b][tid];
    hist[tid + 1024] = g_hist[b][tid + 1024];

    // warp 0: fixed-tree sum of 69 block partials
    if (tid < 32) {
        float4 a0 = g_part[b * BPI + tid];
        float4 a1 = g_part[b * BPI + tid + 32];
        float L = a0.x + a1.x, P = a0.y + a1.y, C = a0.z + a1.z;
        if (tid < BPI - 64) {
            float4 a2 = g_part[b * BPI + tid + 64];
            L += a2.x; P += a2.y; C += a2.z;
        }
        #pragma unroll
        for (int o = 16; o > 0; o >>= 1) {
            L += __shfl_xor_sync(0xFFFFFFFFu, L, o);
            P += __shfl_xor_sync(0xFFFFFFFFu, P, o);
            C += __shfl_xor_sync(0xFFFFFFFFu, C, o);
        }
        if (tid == 0) {
            int K = 3 * (int)(C + 0.5f);
            if (K > AA) K = AA;
            scal[2] = (unsigned)K;
            scal[3] = 0u;
            fscal[8] = L; fscal[9] = P; fscal[10] = C;
        }
    }
    __syncthreads();

    const unsigned K = scal[2];
    float neg_tot = 0.0f;

    if (K > 0) {
        // pass 0 select from prebuilt hist
        select_desc(hist, 2048, 2, K, wscan, &scal[0], &scal[1]);
        const unsigned binB = scal[0];
        unsigned Kr = scal[1];
        __syncthreads();

        // gather candidate indices of the threshold bin
        for (int a = tid; a < AA; a += 1024) {
            if ((__float_as_uint(svals[a]) >> 21) == binB)
                cand[atomicAdd(&scal[3], 1u)] = (unsigned short)a;
        }
        __syncthreads();
        const int C = (int)scal[3];

        // mini pass 1: bits [20:10]
        hist[tid] = 0u; hist[tid + 1024] = 0u;
        __syncthreads();
        for (int i = tid; i < C; i += 1024) {
            unsigned k = __float_as_uint(svals[cand[i]]);
            atomicAdd(&hist[(k >> 10) & 0x7FFu], 1u);
        }
        __syncthreads();
        select_desc(hist, 2048, 2, Kr, wscan, &scal[0], &scal[1]);
        const unsigned sel2 = scal[0];
        Kr = scal[1];
        __syncthreads();

        // mini pass 2: bits [9:0]
        hist[tid] = 0u;
        __syncthreads();
        for (int i = tid; i < C; i += 1024) {
            unsigned k = __float_as_uint(svals[cand[i]]);
            if (((k >> 10) & 0x7FFu) == sel2) atomicAdd(&hist[k & 0x3FFu], 1u);
        }
        __syncthreads();
        select_desc(hist, 1024, 1, Kr, wscan, &scal[0], &scal[1]);
        const unsigned T = (binB << 21) | (sel2 << 10) | scal[0];
        const unsigned r = scal[1];

        // strict-greater sum (deterministic, vectorized)
        float sv = 0.0f;
        for (int i = tid; i < AA4; i += 1024) {
            float4 v = s4[i];
            if (__float_as_uint(v.x) > T) sv += v.x;
            if (__float_as_uint(v.y) > T) sv += v.y;
            if (__float_as_uint(v.z) > T) sv += v.z;
            if (__float_as_uint(v.w) > T) sv += v.w;
        }
        neg_tot = block_reduce_sum(sv, sbuf) + (float)r * __uint_as_float(T);
    }

    // publish per-image results; last block finalizes
    if (tid == 0) {
        g_img[b * 4 + 0] = fscal[8];
        g_img[b * 4 + 1] = fscal[9];
        g_img[b * 4 + 2] = neg_tot;
        g_img[b * 4 + 3] = fscal[10];
        __threadfence();
        unsigned old = atomicAdd(&g_ticket, 1u);
        scal[4] = (old == BB - 1) ? 1u : 0u;
    }
    __syncthreads();

    if (scal[4]) {
        if (tid < 32) {
            float l, p, n, c;
            {
                int i = tid;
                l = g_img[i * 4]; p = g_img[i * 4 + 1];
                n = g_img[i * 4 + 2]; c = g_img[i * 4 + 3];
                i = tid + 32;
                l += g_img[i * 4]; p += g_img[i * 4 + 1];
                n += g_img[i * 4 + 2]; c += g_img[i * 4 + 3];
            }
            #pragma unroll
            for (int o = 16; o > 0; o >>= 1) {
                l += __shfl_xor_sync(0xFFFFFFFFu, l, o);
                p += __shfl_xor_sync(0xFFFFFFFFu, p, o);
                n += __shfl_xor_sync(0xFFFFFFFFu, n, o);
                c += __shfl_xor_sync(0xFFFFFFFFu, c, o);
            }
            if (tid == 0) {
                float N = fmaxf(1.0f, c);
                float loc_loss  = l / N;
                float conf_loss = (p + n) / N;
                out[0] = loc_loss + conf_loss;
                out[1] = loc_loss;
                out[2] = conf_loss;
            }
        }
    }
}

// ---------------------------------------------------------------------------
extern "C" void kernel_launch(void* const* d_in, const int* in_sizes, int n_in,
                              void* d_out, int out_size)
{
    const float4* scores4  = (const float4*)d_in[0];          // [B,A,C] fp32
    const float4* boxes    = (const float4*)d_in[1];          // [B,A,4]
    const int*    labels   = (const int*)d_in[2];             // [B,A]
    const float4* gt_boxes = (const float4*)d_in[3];          // [B,A,4]
    const void*   mask     = d_in[4];                         // [B,A] int32 or bool

    float* out = (float*)d_out;

    cudaFuncSetAttribute(topk_kernel,
                         cudaFuncAttributeMaxDynamicSharedMemorySize, TK_SMEM);

    zero_kernel<<<64, 256>>>();
    probe_kernel<<<64, 256>>>((const int*)mask);
    closs_kernel<<<NBLK1, 128>>>(scores4, labels, boxes, gt_boxes,
                                 (const int*)mask, (const unsigned char*)mask);
    topk_kernel<<<BB, 1024, TK_SMEM>>>(out);
}

// round 8
// speedup vs baseline: 1.0060x; 1.0060x over previous
#include <cuda_runtime.h>
#include <float.h>

// Problem constants
#define BB 64
#define AA 8732
#define CC 81
#define NANCH (BB * AA)            // 558848
#define BPI 69                     // closs blocks per image (69*128 >= 8732)
#define TROWS 128
#define NBLK1 (BB * BPI)           // 4416
#define TILE_F (TROWS * CC)        // 10368 floats
#define TILE_F4 (TILE_F / 4)       // 2592
#define AA4 (AA / 4)               // 2183
#define TOTAL_F4 (NANCH * CC / 4)  // 11316672

// Scratch (no allocations allowed)
__device__ float    g_conf[NANCH];        // conf_neg (masked closs, clamped >= 0)
__device__ float4   g_part[NBLK1];        // per closs-block: {loc, pcl, cnt, -}
__device__ unsigned g_hist[BB][2048];     // per-image 11-bit MSB histogram
__device__ float    g_img[BB * 4];        // per image: loc, pcl, neg_topk, cnt
__device__ int      g_mask_is_bytes;
__device__ unsigned g_ticket;

// ---------------------------------------------------------------------------
// Zero/reset kernel: clears hist + flags (graph replays re-zero everything).
// ---------------------------------------------------------------------------
__global__ void zero_kernel()
{
    const int i = blockIdx.x * blockDim.x + threadIdx.x;   // 16384 threads
    unsigned* h = &g_hist[0][0];
    #pragma unroll
    for (int k = 0; k < 8; k++) h[i + k * 16384] = 0u;
    if (i == 0) { g_mask_is_bytes = 0; g_ticket = 0u; }
}

// ---------------------------------------------------------------------------
// Mask dtype probe over first 16384 words (64KB, in-bounds for both layouts).
// bool-byte mask has ~1300 one-bytes there -> packed words > 1 with certainty.
// ---------------------------------------------------------------------------
__global__ void probe_kernel(const int* __restrict__ m)
{
    const int i = blockIdx.x * blockDim.x + threadIdx.x;   // 16384 threads
    if ((unsigned)m[i] > 1u) atomicOr(&g_mask_is_bytes, 1);
}

// ---------------------------------------------------------------------------
// Kernel 1 (fused): per-anchor CE -> conf_neg + per-image hist + per-block
// partial sums. Staging is a compile-time-unrolled 20-stride float4 copy
// (MLP ~20); tail blocks clamp the source index (ALU-only, loads independent).
// ---------------------------------------------------------------------------
__global__ __launch_bounds__(128) void closs_kernel(const float4* __restrict__ scores4,
                                                    const int* __restrict__ labels,
                                                    const float4* __restrict__ boxes,
                                                    const float4* __restrict__ gtb,
                                                    const int* __restrict__ mask_i,
                                                    const unsigned char* __restrict__ mask_b)
{
    __shared__ __align__(16) float tile[TILE_F];   // 41472 B
    __shared__ float sred[12];

    const int img  = blockIdx.x / BPI;
    const int blk  = blockIdx.x - img * BPI;
    const int row0 = blk * TROWS;
    const int rows = min(TROWS, AA - row0);        // 128; tail block 28
    const int t    = threadIdx.x;
    const int anchor = img * AA + row0 + t;

    const unsigned base_f4 = (unsigned)(((size_t)img * AA + row0) * CC / 4);
    float4* t4 = (float4*)tile;

    // 2592 float4: 20 full strides + 32 tail; source clamped for global tail.
    #pragma unroll
    for (int i = 0; i < 20; i++) {
        unsigned gi = min(base_f4 + (unsigned)(t + i * 128), (unsigned)(TOTAL_F4 - 1));
        t4[t + i * 128] = scores4[gi];
    }
    if (t < TILE_F4 - 2560) {
        unsigned gi = min(base_f4 + (unsigned)(t + 2560), (unsigned)(TOTAL_F4 - 1));
        t4[t + 2560] = scores4[gi];
    }

    // independent loads (overlap with staging)
    int lab = 0; bool mk = false;
    if (t < rows) {
        lab = labels[anchor];
        mk  = g_mask_is_bytes ? (mask_b[anchor] != 0) : (mask_i[anchor] != 0);
    }
    __syncthreads();

    float cnt = 0.0f, pcl = 0.0f, loc = 0.0f;
    if (t < rows) {
        const float* p = tile + t * CC;   // stride 81 (odd) -> conflict-free
        float s0 = 0.0f, s1 = 0.0f, s2 = 0.0f, s3 = 0.0f;
        #pragma unroll
        for (int c = 0; c < 80; c += 4) {
            s0 += __expf(p[c]);
            s1 += __expf(p[c + 1]);
            s2 += __expf(p[c + 2]);
            s3 += __expf(p[c + 3]);
        }
        s0 += __expf(p[80]);
        const float cl = __logf((s0 + s1) + (s2 + s3)) - p[lab];

        const float conf = mk ? 0.0f : fmaxf(cl, 0.0f);   // CE >= 0 mathematically
        g_conf[anchor] = conf;
        atomicAdd(&g_hist[img][__float_as_uint(conf) >> 21], 1u);

        if (mk) {
            cnt = 1.0f; pcl = cl;
            float4 bx = boxes[anchor], gx = gtb[anchor];
            float d, ad;
            d = bx.x - gx.x; ad = fabsf(d); loc += (ad < 1.0f) ? 0.5f*d*d : ad - 0.5f;
            d = bx.y - gx.y; ad = fabsf(d); loc += (ad < 1.0f) ? 0.5f*d*d : ad - 0.5f;
            d = bx.z - gx.z; ad = fabsf(d); loc += (ad < 1.0f) ? 0.5f*d*d : ad - 0.5f;
            d = bx.w - gx.w; ad = fabsf(d); loc += (ad < 1.0f) ? 0.5f*d*d : ad - 0.5f;
        }
    }

    #pragma unroll
    for (int o = 16; o > 0; o >>= 1) {
        cnt += __shfl_xor_sync(0xFFFFFFFFu, cnt, o);
        pcl += __shfl_xor_sync(0xFFFFFFFFu, pcl, o);
        loc += __shfl_xor_sync(0xFFFFFFFFu, loc, o);
    }
    if ((t & 31) == 0) {
        const int w = t >> 5;
        sred[w * 3 + 0] = loc; sred[w * 3 + 1] = pcl; sred[w * 3 + 2] = cnt;
    }
    __syncthreads();
    if (t == 0) {
        g_part[blockIdx.x] = make_float4(sred[0] + sred[3] + sred[6] + sred[9],
                                         sred[1] + sred[4] + sred[7] + sred[10],
                                         sred[2] + sred[5] + sred[8] + sred[11],
                                         0.0f);
    }
}

// ---------------------------------------------------------------------------
// Block reductions / scans (1024 threads, deterministic fixed trees).
// ---------------------------------------------------------------------------
__device__ __forceinline__ float block_reduce_sum(float v, float* sbuf)
{
    const int lane = threadIdx.x & 31, wid = threadIdx.x >> 5;
    #pragma unroll
    for (int o = 16; o > 0; o >>= 1) v += __shfl_xor_sync(0xFFFFFFFFu, v, o);
    if (lane == 0) sbuf[wid] = v;
    __syncthreads();
    if (wid == 0) {
        v = sbuf[lane];
        #pragma unroll
        for (int o = 16; o > 0; o >>= 1) v += __shfl_xor_sync(0xFFFFFFFFu, v, o);
        if (lane == 0) sbuf[0] = v;
    }
    __syncthreads();
    float r = sbuf[0];
    __syncthreads();
    return r;
}

__device__ __forceinline__ int block_excl_scan(int v, int* wsums, unsigned* total)
{
    const int lane = threadIdx.x & 31, wid = threadIdx.x >> 5;
    int incl = v;
    #pragma unroll
    for (int st = 1; st < 32; st <<= 1) {
        int o = __shfl_up_sync(0xFFFFFFFFu, incl, st);
        if (lane >= st) incl += o;
    }
    if (lane == 31) wsums[wid] = incl;
    __syncthreads();
    if (wid == 0) {
        int wv = wsums[lane], wi = wv;
        #pragma unroll
        for (int st = 1; st < 32; st <<= 1) {
            int o = __shfl_up_sync(0xFFFFFFFFu, wi, st);
            if (lane >= st) wi += o;
        }
        wsums[lane] = wi - wv;
    }
    __syncthreads();
    int excl = wsums[wid] + incl - v;
    if (threadIdx.x == 1023) *total = (unsigned)(excl + v);
    __syncthreads();
    return excl;
}

// ---------------------------------------------------------------------------
// Descending-bin radix selection over NB bins (cs bins/thread, cs in {1,2}).
// ---------------------------------------------------------------------------
__device__ __forceinline__ void select_desc(const unsigned* __restrict__ hist,
                                            int NB, int cs, unsigned Kr,
                                            unsigned* wscan,
                                            unsigned* sh_sel, unsigned* sh_rr)
{
    const int tid = threadIdx.x, lane = tid & 31, wid = tid >> 5;
    unsigned cv0 = 0, cv1 = 0, v;
    const int hi = NB - 1 - cs * tid;
    cv0 = hist[hi];
    if (cs == 2) cv1 = hist[hi - 1];
    v = cv0 + cv1;

    unsigned incl = v;
    #pragma unroll
    for (int st = 1; st < 32; st <<= 1) {
        unsigned o = __shfl_up_sync(0xFFFFFFFFu, incl, st);
        if (lane >= st) incl += o;
    }
    if (lane == 31) wscan[wid] = incl;
    __syncthreads();
    if (wid == 0) {
        unsigned wv = wscan[lane], wi = wv;
        #pragma unroll
        for (int st = 1; st < 32; st <<= 1) {
            unsigned o = __shfl_up_sync(0xFFFFFFFFu, wi, st);
            if (lane >= st) wi += o;
        }
        wscan[lane] = wi - wv;
    }
    __syncthreads();
    const unsigned excl  = wscan[wid] + incl - v;
    const unsigned inclT = wscan[wid] + incl;
    if (excl < Kr && inclT >= Kr) {
        unsigned cum = excl;
        if (cum + cv0 >= Kr)      { *sh_sel = (unsigned)hi;       *sh_rr = Kr - cum; }
        else                      { cum += cv0;
                                    *sh_sel = (unsigned)(hi - 1); *sh_rr = Kr - cum; }
    }
    __syncthreads();
}

// ---------------------------------------------------------------------------
// Kernel 2: one block per image. Single full sweep over conf:
//  1) select threshold bin B from prebuilt hist (no value sweep needed)
//  2) sweep conf once: sum values in bins > B; collect bin-B candidates
//     (<=12/thread in registers) -> deterministic positions via block scan
//  3) refine T over candidates (two mini radix passes)
//  4) final = sum_above + sum(cand > T) + r*T. Ticket block finalizes output.
// ---------------------------------------------------------------------------
__global__ __launch_bounds__(1024) void topk_kernel(float* __restrict__ out)
{
    __shared__ unsigned hist[2048];
    __shared__ float    candv[AA];       // worst case all candidates (34928 B)
    __shared__ unsigned wscan[32];
    __shared__ float    sbuf[32];
    __shared__ int      wsums[32];
    __shared__ unsigned scal[8];
    __shared__ float    fscal[4];

    const int b = blockIdx.x, tid = threadIdx.x;

    // load prebuilt histogram
    hist[tid]        = g_hist[b][tid];
    hist[tid + 1024] = g_hist[b][tid + 1024];

    // warp 0: fixed-tree sum of 69 block partials -> K, loc, pcl, cnt
    if (tid < 32) {
        float4 a0 = g_part[b * BPI + tid];
        float4 a1 = g_part[b * BPI + tid + 32];
        float L = a0.x + a1.x, P = a0.y + a1.y, C = a0.z + a1.z;
        if (tid < BPI - 64) {
            float4 a2 = g_part[b * BPI + tid + 64];
            L += a2.x; P += a2.y; C += a2.z;
        }
        #pragma unroll
        for (int o = 16; o > 0; o >>= 1) {
            L += __shfl_xor_sync(0xFFFFFFFFu, L, o);
            P += __shfl_xor_sync(0xFFFFFFFFu, P, o);
            C += __shfl_xor_sync(0xFFFFFFFFu, C, o);
        }
        if (tid == 0) {
            int K = 3 * (int)(C + 0.5f);
            if (K > AA) K = AA;
            scal[2] = (unsigned)K;
            fscal[0] = L; fscal[1] = P; fscal[2] = C;
        }
    }
    __syncthreads();

    const unsigned K = scal[2];
    float neg_tot = 0.0f;

    if (K > 0) {
        // 1) threshold bin from prebuilt hist
        select_desc(hist, 2048, 2, K, wscan, &scal[0], &scal[1]);
        const unsigned binB = scal[0];
        unsigned Kr = scal[1];
        __syncthreads();

        // 2) single sweep: sum bins>binB, collect binB candidates in registers
        const float4* c4 = (const float4*)(g_conf + b * AA);
        float sum_hi = 0.0f;
        float cv[12]; int cn = 0;
        #pragma unroll
        for (int s = 0; s < 3; s++) {
            const int i = tid + (s << 10);
            if (i < AA4) {
                float4 v = c4[i];
                #define CHK(X) { unsigned bn = __float_as_uint(X) >> 21;            \
                                 if (bn > binB) sum_hi += X;                         \
                                 else if (bn == binB) cv[cn++] = X; }
                CHK(v.x) CHK(v.y) CHK(v.z) CHK(v.w)
                #undef CHK
            }
        }
        int pos = block_excl_scan(cn, wsums, &scal[3]);
        for (int j = 0; j < cn; j++) candv[pos + j] = cv[j];
        __syncthreads();
        const int C = (int)scal[3];

        // 3a) mini pass: bits [20:10]
        hist[tid] = 0u; hist[tid + 1024] = 0u;
        __syncthreads();
        for (int i = tid; i < C; i += 1024)
            atomicAdd(&hist[(__float_as_uint(candv[i]) >> 10) & 0x7FFu], 1u);
        __syncthreads();
        select_desc(hist, 2048, 2, Kr, wscan, &scal[0], &scal[1]);
        const unsigned sel2 = scal[0];
        Kr = scal[1];
        __syncthreads();

        // 3b) mini pass: bits [9:0]
        hist[tid] = 0u;
        __syncthreads();
        for (int i = tid; i < C; i += 1024) {
            unsigned k = __float_as_uint(candv[i]);
            if (((k >> 10) & 0x7FFu) == sel2) atomicAdd(&hist[k & 0x3FFu], 1u);
        }
        __syncthreads();
        select_desc(hist, 1024, 1, Kr, wscan, &scal[0], &scal[1]);
        const unsigned T = (binB << 21) | (sel2 << 10) | scal[0];
        const unsigned r = scal[1];

        // 4) candidates strictly above T (deterministic order) + sum_hi
        float cs = 0.0f;
        for (int i = tid; i < C; i += 1024) {
            float v = candv[i];
            if (__float_as_uint(v) > T) cs += v;
        }
        neg_tot = block_reduce_sum(sum_hi + cs, sbuf) + (float)r * __uint_as_float(T);
    }

    // publish per-image results; last block finalizes
    if (tid == 0) {
        g_img[b * 4 + 0] = fscal[0];
        g_img[b * 4 + 1] = fscal[1];
        g_img[b * 4 + 2] = neg_tot;
        g_img[b * 4 + 3] = fscal[2];
        __threadfence();
        unsigned old = atomicAdd(&g_ticket, 1u);
        scal[4] = (old == BB - 1) ? 1u : 0u;
    }
    __syncthreads();

    if (scal[4]) {
        if (tid < 32) {
            float l, p, n, c;
            {
                int i = tid;
                l = g_img[i * 4]; p = g_img[i * 4 + 1];
                n = g_img[i * 4 + 2]; c = g_img[i * 4 + 3];
                i = tid + 32;
                l += g_img[i * 4]; p += g_img[i * 4 + 1];
                n += g_img[i * 4 + 2]; c += g_img[i * 4 + 3];
            }
            #pragma unroll
            for (int o = 16; o > 0; o >>= 1) {
                l += __shfl_xor_sync(0xFFFFFFFFu, l, o);
                p += __shfl_xor_sync(0xFFFFFFFFu, p, o);
                n += __shfl_xor_sync(0xFFFFFFFFu, n, o);
                c += __shfl_xor_sync(0xFFFFFFFFu, c, o);
            }
            if (tid == 0) {
                float N = fmaxf(1.0f, c);
                float loc_loss  = l / N;
                float conf_loss = (p + n) / N;
                out[0] = loc_loss + conf_loss;
                out[1] = loc_loss;
                out[2] = conf_loss;
            }
        }
    }
}

// ---------------------------------------------------------------------------
extern "C" void kernel_launch(void* const* d_in, const int* in_sizes, int n_in,
                              void* d_out, int out_size)
{
    const float4* scores4  = (const float4*)d_in[0];          // [B,A,C] fp32
    const float4* boxes    = (const float4*)d_in[1];          // [B,A,4]
    const int*    labels   = (const int*)d_in[2];             // [B,A]
    const float4* gt_boxes = (const float4*)d_in[3];          // [B,A,4]
    const void*   mask     = d_in[4];                         // [B,A] int32 or bool

    float* out = (float*)d_out;

    zero_kernel<<<64, 256>>>();
    probe_kernel<<<64, 256>>>((const int*)mask);
    closs_kernel<<<NBLK1, 128>>>(scores4, labels, boxes, gt_boxes,
                                 (const int*)mask, (const unsigned char*)mask);
    topk_kernel<<<BB, 1024>>>(out);
}

// round 9
// speedup vs baseline: 1.0393x; 1.0331x over previous
#include <cuda_runtime.h>
#include <cuda_pipeline.h>
#include <float.h>

// Problem constants
#define BB 64
#define AA 8732
#define CC 81
#define NANCH (BB * AA)            // 558848
#define BPI 69                     // closs blocks per image (68 full + 1 tail)
#define TROWS 128
#define NBLK1 (BB * BPI)           // 4416
#define TILE_F (TROWS * CC)        // 10368 floats
#define TILE_F4 (TILE_F / 4)       // 2592
#define AA4 (AA / 4)               // 2183
#define TOTAL_F4 (NANCH * CC / 4)  // 11316672
#define TAIL_ROWS (AA - 68 * TROWS)        // 28
#define TAIL_F4 (TAIL_ROWS * CC / 4)       // 567

// Scratch (no allocations allowed)
__device__ float    g_conf[NANCH];        // conf_neg (masked closs, clamped >= 0)
__device__ float4   g_part[NBLK1];        // per closs-block: {loc, pcl, cnt, -}
__device__ unsigned g_hist[BB][2048];     // per-image 11-bit MSB histogram
__device__ float    g_img[BB * 4];        // per image: loc, pcl, neg_topk, cnt
__device__ int      g_mask_is_bytes;
__device__ unsigned g_ticket;

// ---------------------------------------------------------------------------
// Zero + probe kernel (merged): clears hist/flags and probes mask dtype.
// 16384 threads: 8 hist words each (131072 total) + 1 probe word each.
// bool-byte mask has ~1300 one-bytes in the first 64KB -> certain verdict.
// ---------------------------------------------------------------------------
__global__ void zero_probe_kernel(const int* __restrict__ m)
{
    const int i = blockIdx.x * blockDim.x + threadIdx.x;   // 16384 threads
    unsigned* h = &g_hist[0][0];
    #pragma unroll
    for (int k = 0; k < 8; k++) h[i + k * 16384] = 0u;
    if (i == 0) g_ticket = 0u;
    if ((unsigned)m[i] > 1u) atomicOr(&g_mask_is_bytes, 1);
    else if (i == 1) atomicAnd(&g_mask_is_bytes, 1);  // no-op keeper
    if (i == 0 && (unsigned)m[0] <= 1u) { /* int32 path stays if never set */ }
}

// reset flag kernel (must run before probe writes; separate tiny launch)
__global__ void flag_reset_kernel() { g_mask_is_bytes = 0; }

// ---------------------------------------------------------------------------
// Kernel 1 (fused): per-anchor CE -> conf_neg + per-image hist + per-block
// partial sums. Full blocks (68/69) use pure imm-offset unrolled staging
// (MLP ~21, no clamps); only the per-image tail block (28 rows) clamps.
// ---------------------------------------------------------------------------
__global__ __launch_bounds__(128) void closs_kernel(const float4* __restrict__ scores4,
                                                    const int* __restrict__ labels,
                                                    const float4* __restrict__ boxes,
                                                    const float4* __restrict__ gtb,
                                                    const int* __restrict__ mask_i,
                                                    const unsigned char* __restrict__ mask_b)
{
    __shared__ __align__(16) float tile[TILE_F];   // 41472 B
    __shared__ float sred[12];

    const int img  = blockIdx.x / BPI;
    const int blk  = blockIdx.x - img * BPI;
    const int row0 = blk * TROWS;
    const int rows = (blk == BPI - 1) ? TAIL_ROWS : TROWS;
    const int t    = threadIdx.x;
    const int anchor = img * AA + row0 + t;

    const float4* src = scores4 + ((size_t)img * AA + row0) * CC / 4;  // f4-aligned
    float4* t4 = (float4*)tile;

    if (rows == TROWS) {
        // 2592 float4: 20 full strides + 32 tail, pure imm-offset loads
        #pragma unroll
        for (int i = 0; i < 20; i++)
            t4[t + i * 128] = src[t + i * 128];
        if (t < TILE_F4 - 2560)
            t4[t + 2560] = src[t + 2560];
    } else {
        // tail block: 567 float4 needed; stage 5 strides (640), clamped
        const unsigned base_f4 = (unsigned)(((size_t)img * AA + row0) * CC / 4);
        #pragma unroll
        for (int i = 0; i < 5; i++) {
            unsigned gi = min(base_f4 + (unsigned)(t + i * 128),
                              (unsigned)(TOTAL_F4 - 1));
            t4[t + i * 128] = scores4[gi];
        }
    }

    // independent loads (overlap with staging)
    int lab = 0; bool mk = false;
    if (t < rows) {
        lab = labels[anchor];
        mk  = g_mask_is_bytes ? (mask_b[anchor] != 0) : (mask_i[anchor] != 0);
    }
    __syncthreads();

    float cnt = 0.0f, pcl = 0.0f, loc = 0.0f;
    if (t < rows) {
        const float* p = tile + t * CC;   // stride 81 (odd) -> conflict-free
        float s0 = 0.0f, s1 = 0.0f, s2 = 0.0f, s3 = 0.0f;
        #pragma unroll
        for (int c = 0; c < 80; c += 4) {
            s0 += __expf(p[c]);
            s1 += __expf(p[c + 1]);
            s2 += __expf(p[c + 2]);
            s3 += __expf(p[c + 3]);
        }
        s0 += __expf(p[80]);
        const float cl = __logf((s0 + s1) + (s2 + s3)) - p[lab];

        const float conf = mk ? 0.0f : fmaxf(cl, 0.0f);   // CE >= 0 mathematically
        g_conf[anchor] = conf;
        atomicAdd(&g_hist[img][__float_as_uint(conf) >> 21], 1u);

        if (mk) {
            cnt = 1.0f; pcl = cl;
            float4 bx = boxes[anchor], gx = gtb[anchor];
            float d, ad;
            d = bx.x - gx.x; ad = fabsf(d); loc += (ad < 1.0f) ? 0.5f*d*d : ad - 0.5f;
            d = bx.y - gx.y; ad = fabsf(d); loc += (ad < 1.0f) ? 0.5f*d*d : ad - 0.5f;
            d = bx.z - gx.z; ad = fabsf(d); loc += (ad < 1.0f) ? 0.5f*d*d : ad - 0.5f;
            d = bx.w - gx.w; ad = fabsf(d); loc += (ad < 1.0f) ? 0.5f*d*d : ad - 0.5f;
        }
    }

    #pragma unroll
    for (int o = 16; o > 0; o >>= 1) {
        cnt += __shfl_xor_sync(0xFFFFFFFFu, cnt, o);
        pcl += __shfl_xor_sync(0xFFFFFFFFu, pcl, o);
        loc += __shfl_xor_sync(0xFFFFFFFFu, loc, o);
    }
    if ((t & 31) == 0) {
        const int w = t >> 5;
        sred[w * 3 + 0] = loc; sred[w * 3 + 1] = pcl; sred[w * 3 + 2] = cnt;
    }
    __syncthreads();
    if (t == 0) {
        g_part[blockIdx.x] = make_float4(sred[0] + sred[3] + sred[6] + sred[9],
                                         sred[1] + sred[4] + sred[7] + sred[10],
                                         sred[2] + sred[5] + sred[8] + sred[11],
                                         0.0f);
    }
}

// ---------------------------------------------------------------------------
// Block reduction (1024 threads, deterministic fixed tree).
// ---------------------------------------------------------------------------
__device__ __forceinline__ float block_reduce_sum(float v, float* sbuf)
{
    const int lane = threadIdx.x & 31, wid = threadIdx.x >> 5;
    #pragma unroll
    for (int o = 16; o > 0; o >>= 1) v += __shfl_xor_sync(0xFFFFFFFFu, v, o);
    if (lane == 0) sbuf[wid] = v;
    __syncthreads();
    if (wid == 0) {
        v = sbuf[lane];
        #pragma unroll
        for (int o = 16; o > 0; o >>= 1) v += __shfl_xor_sync(0xFFFFFFFFu, v, o);
        if (lane == 0) sbuf[0] = v;
    }
    __syncthreads();
    float r = sbuf[0];
    __syncthreads();
    return r;
}

// ---------------------------------------------------------------------------
// Descending-bin radix selection over NB bins (cs bins/thread, cs in {1,2}).
// Deterministic (single boundary thread writes).
// ---------------------------------------------------------------------------
__device__ __forceinline__ void select_desc(const unsigned* __restrict__ hist,
                                            int NB, int cs, unsigned Kr,
                                            unsigned* wscan,
                                            unsigned* sh_sel, unsigned* sh_rr)
{
    const int tid = threadIdx.x, lane = tid & 31, wid = tid >> 5;
    unsigned cv0 = 0, cv1 = 0, v;
    const int hi = NB - 1 - cs * tid;
    cv0 = hist[hi];
    if (cs == 2) cv1 = hist[hi - 1];
    v = cv0 + cv1;

    unsigned incl = v;
    #pragma unroll
    for (int st = 1; st < 32; st <<= 1) {
        unsigned o = __shfl_up_sync(0xFFFFFFFFu, incl, st);
        if (lane >= st) incl += o;
    }
    if (lane == 31) wscan[wid] = incl;
    __syncthreads();
    if (wid == 0) {
        unsigned wv = wscan[lane], wi = wv;
        #pragma unroll
        for (int st = 1; st < 32; st <<= 1) {
            unsigned o = __shfl_up_sync(0xFFFFFFFFu, wi, st);
            if (lane >= st) wi += o;
        }
        wscan[lane] = wi - wv;
    }
    __syncthreads();
    const unsigned excl  = wscan[wid] + incl - v;
    const unsigned inclT = wscan[wid] + incl;
    if (excl < Kr && inclT >= Kr) {
        unsigned cum = excl;
        if (cum + cv0 >= Kr)      { *sh_sel = (unsigned)hi;       *sh_rr = Kr - cum; }
        else                      { cum += cv0;
                                    *sh_sel = (unsigned)(hi - 1); *sh_rr = Kr - cum; }
    }
    __syncthreads();
}

// ---------------------------------------------------------------------------
// Kernel 2: one block per image. conf loaded to smem via cp.async at entry
// (overlaps partials+hist+binB select). Mini radix passes filter smem
// directly (no candidate gather, no LMEM). Ticket block finalizes output.
// ---------------------------------------------------------------------------
__global__ __launch_bounds__(1024) void topk_kernel(float* __restrict__ out)
{
    __shared__ __align__(16) float svals[AA];    // 34928 B
    __shared__ unsigned hist[2048];              // 8192 B
    __shared__ unsigned wscan[32];
    __shared__ float    sbuf[32];
    __shared__ unsigned scal[8];
    __shared__ float    fscal[4];

    const int b = blockIdx.x, tid = threadIdx.x;

    // 1) async-load conf into smem (2183 f4), overlapped with setup below
    {
        const float4* c4 = (const float4*)(g_conf + b * AA);
        float4* s4 = (float4*)svals;
        __pipeline_memcpy_async(&s4[tid],        &c4[tid],        16);
        __pipeline_memcpy_async(&s4[tid + 1024], &c4[tid + 1024], 16);
        if (tid < AA4 - 2048)
            __pipeline_memcpy_async(&s4[tid + 2048], &c4[tid + 2048], 16);
        __pipeline_commit();
    }

    // 2) load prebuilt histogram
    hist[tid]        = g_hist[b][tid];
    hist[tid + 1024] = g_hist[b][tid + 1024];

    // 3) warp 0: fixed-tree sum of 69 block partials -> K, loc, pcl, cnt
    if (tid < 32) {
        float4 a0 = g_part[b * BPI + tid];
        float4 a1 = g_part[b * BPI + tid + 32];
        float L = a0.x + a1.x, P = a0.y + a1.y, C = a0.z + a1.z;
        if (tid < BPI - 64) {
            float4 a2 = g_part[b * BPI + tid + 64];
            L += a2.x; P += a2.y; C += a2.z;
        }
        #pragma unroll
        for (int o = 16; o > 0; o >>= 1) {
            L += __shfl_xor_sync(0xFFFFFFFFu, L, o);
            P += __shfl_xor_sync(0xFFFFFFFFu, P, o);
            C += __shfl_xor_sync(0xFFFFFFFFu, C, o);
        }
        if (tid == 0) {
            int K = 3 * (int)(C + 0.5f);
            if (K > AA) K = AA;
            scal[2] = (unsigned)K;
            fscal[0] = L; fscal[1] = P; fscal[2] = C;
        }
    }
    __syncthreads();

    const unsigned K = scal[2];
    float neg_tot = 0.0f;

    if (K > 0) {
        // 4) threshold bin from prebuilt hist (conf still in flight)
        select_desc(hist, 2048, 2, K, wscan, &scal[0], &scal[1]);
        const unsigned binB = scal[0];
        unsigned Kr = scal[1];

        __pipeline_wait_prior(0);
        __syncthreads();   // conf landed + select published

        // 5a) mini pass: filter binB, hist bits [20:10] (smem sweep)
        hist[tid] = 0u; hist[tid + 1024] = 0u;
        __syncthreads();
        #pragma unroll
        for (int s = 0; s < 9; s++) {
            const int a = tid + (s << 10);
            if (a < AA) {
                unsigned k = __float_as_uint(svals[a]);
                if ((k >> 21) == binB) atomicAdd(&hist[(k >> 10) & 0x7FFu], 1u);
            }
        }
        __syncthreads();
        select_desc(hist, 2048, 2, Kr, wscan, &scal[0], &scal[1]);
        const unsigned pfx22 = (binB << 11) | scal[0];
        Kr = scal[1];
        __syncthreads();

        // 5b) mini pass: filter pfx22, hist bits [9:0]
        hist[tid] = 0u;
        __syncthreads();
        #pragma unroll
        for (int s = 0; s < 9; s++) {
            const int a = tid + (s << 10);
            if (a < AA) {
                unsigned k = __float_as_uint(svals[a]);
                if ((k >> 10) == pfx22) atomicAdd(&hist[k & 0x3FFu], 1u);
            }
        }
        __syncthreads();
        select_desc(hist, 1024, 1, Kr, wscan, &scal[0], &scal[1]);
        const unsigned T = (pfx22 << 10) | scal[0];
        const unsigned r = scal[1];

        // 6) strict-greater sum (deterministic, vectorized smem sweep)
        float sv = 0.0f;
        const float4* s4 = (const float4*)svals;
        #pragma unroll
        for (int s = 0; s < 3; s++) {
            const int i = tid + (s << 10);
            if (i < AA4) {
                float4 v = s4[i];
                if (__float_as_uint(v.x) > T) sv += v.x;
                if (__float_as_uint(v.y) > T) sv += v.y;
                if (__float_as_uint(v.z) > T) sv += v.z;
                if (__float_as_uint(v.w) > T) sv += v.w;
            }
        }
        neg_tot = block_reduce_sum(sv, sbuf) + (float)r * __uint_as_float(T);
    } else {
        __pipeline_wait_prior(0);
    }

    // 7) publish per-image results; last block finalizes
    if (tid == 0) {
        g_img[b * 4 + 0] = fscal[0];
        g_img[b * 4 + 1] = fscal[1];
        g_img[b * 4 + 2] = neg_tot;
        g_img[b * 4 + 3] = fscal[2];
        __threadfence();
        unsigned old = atomicAdd(&g_ticket, 1u);
        scal[4] = (old == BB - 1) ? 1u : 0u;
    }
    __syncthreads();

    if (scal[4]) {
        if (tid < 32) {
            float l, p, n, c;
            {
                int i = tid;
                l = g_img[i * 4]; p = g_img[i * 4 + 1];
                n = g_img[i * 4 + 2]; c = g_img[i * 4 + 3];
                i = tid + 32;
                l += g_img[i * 4]; p += g_img[i * 4 + 1];
                n += g_img[i * 4 + 2]; c += g_img[i * 4 + 3];
            }
            #pragma unroll
            for (int o = 16; o > 0; o >>= 1) {
                l += __shfl_xor_sync(0xFFFFFFFFu, l, o);
                p += __shfl_xor_sync(0xFFFFFFFFu, p, o);
                n += __shfl_xor_sync(0xFFFFFFFFu, n, o);
                c += __shfl_xor_sync(0xFFFFFFFFu, c, o);
            }
            if (tid == 0) {
                float N = fmaxf(1.0f, c);
                float loc_loss  = l / N;
                float conf_loss = (p + n) / N;
                out[0] = loc_loss + conf_loss;
                out[1] = loc_loss;
                out[2] = conf_loss;
            }
        }
    }
}

// ---------------------------------------------------------------------------
extern "C" void kernel_launch(void* const* d_in, const int* in_sizes, int n_in,
                              void* d_out, int out_size)
{
    const float4* scores4  = (const float4*)d_in[0];          // [B,A,C] fp32
    const float4* boxes    = (const float4*)d_in[1];          // [B,A,4]
    const int*    labels   = (const int*)d_in[2];             // [B,A]
    const float4* gt_boxes = (const float4*)d_in[3];          // [B,A,4]
    const void*   mask     = d_in[4];                         // [B,A] int32 or bool

    float* out = (float*)d_out;

    flag_reset_kernel<<<1, 1>>>();
    zero_probe_kernel<<<64, 256>>>((const int*)mask);
    closs_kernel<<<NBLK1, 128>>>(scores4, labels, boxes, gt_boxes,
                                 (const int*)mask, (const unsigned char*)mask);
    topk_kernel<<<BB, 1024>>>(out);
}